// round 6
// baseline (speedup 1.0000x reference)
#include <cuda_runtime.h>
#include <math.h>

#define NNODES 65536
#define DF 64
#define NEDGES 1048576
#define CAP 64            // per-node bin capacity (Poisson(16); never overflowed)
#define CHUNK 16

// ---- static scratch (no device allocs allowed) ----
__device__ int   g_cnt[NNODES];            // per-node fill cursor / count
__device__ int2  g_ew[NNODES * CAP];       // bins: (.x = src, .y = bits of (1-alpha)*val)

// ---------------------------------------------------------------------------
// 1) zero cursors (globals dirty across graph replays)
// ---------------------------------------------------------------------------
__global__ void k_zero() {
    g_cnt[blockIdx.x * blockDim.x + threadIdx.x] = 0;
}

// ---------------------------------------------------------------------------
// 2) bin edges by destination; fold (1-alpha)*val into stored weight.
//    4 edges per thread via int4/float4 loads.
// ---------------------------------------------------------------------------
__global__ void k_bin(const int*   __restrict__ src,
                      const int*   __restrict__ dst,
                      const float* __restrict__ val,
                      const float* __restrict__ alpha_p) {
    const int t = blockIdx.x * blockDim.x + threadIdx.x;   // 0 .. NEDGES/4-1
    const float oma = 1.0f - __ldg(alpha_p);
    int4   s4 = __ldg((const int4*)src + t);
    int4   d4 = __ldg((const int4*)dst + t);
    float4 v4 = __ldg((const float4*)val + t);

    int p0 = atomicAdd(&g_cnt[d4.x], 1);
    int p1 = atomicAdd(&g_cnt[d4.y], 1);
    int p2 = atomicAdd(&g_cnt[d4.z], 1);
    int p3 = atomicAdd(&g_cnt[d4.w], 1);
    if (p0 < CAP) g_ew[(size_t)d4.x * CAP + p0] = make_int2(s4.x, __float_as_int(oma * v4.x));
    if (p1 < CAP) g_ew[(size_t)d4.y * CAP + p1] = make_int2(s4.y, __float_as_int(oma * v4.y));
    if (p2 < CAP) g_ew[(size_t)d4.z * CAP + p2] = make_int2(s4.z, __float_as_int(oma * v4.z));
    if (p3 < CAP) g_ew[(size_t)d4.w * CAP + p3] = make_int2(s4.w, __float_as_int(oma * v4.w));
}

// ---------------------------------------------------------------------------
// 3) FUSED gather-aggregate + residual + identity-mapped GEMM.
//    Block = 256 threads owns 64 nodes.
//    Phase A: warp per node (8 nodes/warp), lane owns 2 cols; batched LDGs,
//             edge records staged in shared; rows -> shared (16 KB).
//    Phase B: GEMM on the 64 shared rows: thread (r4=tid>>6, j=tid&63),
//             W column in 64 regs, broadcast LDS.128 row reads.
//    Gather (LTS-bound) and GEMM (FMA-bound) overlap across co-resident
//    blocks/warps on each SM.
// ---------------------------------------------------------------------------
__global__ void __launch_bounds__(256, 2)
k_fused(const float* __restrict__ feature,
        const float* __restrict__ x,
        const float* __restrict__ weight,
        const float* __restrict__ alpha_p,
        const float* __restrict__ lamda_p,
        const int*   __restrict__ l_p,
        float*       __restrict__ out) {
    __shared__ float Ws[DF * DF];                       // 16 KB
    __shared__ __align__(16) float rows[64][DF];        // 16 KB
    __shared__ int2 sew[8][CAP];                        // 4 KB

    const int tid  = threadIdx.x;
    const int wid  = tid >> 5;
    const int lane = tid & 31;

    // W -> shared (consumed after the phase barrier)
    const float4* w4 = (const float4*)weight;
#pragma unroll
    for (int i = 0; i < 4; i++)
        ((float4*)Ws)[tid + 256 * i] = __ldg(w4 + tid + 256 * i);

    // ---------------- Phase A: gather 8 nodes per warp ----------------
    const float  alpha = __ldg(alpha_p);
    const float2* x2   = (const float2*)x;
    const int base = blockIdx.x * 64 + wid * 8;

    for (int t = 0; t < 8; t++) {
        const int node = base + t;
        int cnt = g_cnt[node];
        if (cnt > CAP) cnt = CAP;
        const int padded = (cnt + CHUNK - 1) & ~(CHUNK - 1);

        const int2* row = g_ew + (size_t)node * CAP;
        __syncwarp();                                   // prior-iter readers done
        if (lane < cnt)      sew[wid][lane]      = __ldg(row + lane);
        if (lane + 32 < cnt) sew[wid][lane + 32] = __ldg(row + lane + 32);
        for (int i = cnt + lane; i < padded; i += 32)
            sew[wid][i] = make_int2(0, 0);              // src 0, weight 0 -> no-op
        __syncwarp();

        float2 f = __ldg((const float2*)feature + (size_t)node * 32 + lane);
        float2 acc = make_float2(alpha * f.x, alpha * f.y);

        for (int cb = 0; cb < padded; cb += CHUNK) {
            int2 e[CHUNK];
#pragma unroll
            for (int i = 0; i < CHUNK; i++) e[i] = sew[wid][cb + i];  // LDS broadcast
            float2 xv[CHUNK];
#pragma unroll
            for (int i = 0; i < CHUNK; i++)                           // 16 LDGs in flight
                xv[i] = __ldg(&x2[(size_t)e[i].x * 32 + lane]);
#pragma unroll
            for (int i = 0; i < CHUNK; i++) {
                float w = __int_as_float(e[i].y);
                acc.x = fmaf(w, xv[i].x, acc.x);
                acc.y = fmaf(w, xv[i].y, acc.y);
            }
        }

        ((float2*)rows[wid * 8 + t])[lane] = acc;       // conflict-free
    }

    __syncthreads();

    // ---------------- Phase B: out = (1-b)*rows + b*(rows @ W) --------
    const int j  = tid & 63;
    const int r4 = tid >> 6;

    float wcol[DF];
#pragma unroll
    for (int k = 0; k < DF; k++) wcol[k] = Ws[k * DF + j];

    const float lam  = __ldg(lamda_p);
    const int   l    = (l_p != nullptr) ? __ldg(l_p) : 1;
    const float beta = logf(lam / (float)l + 1.0f);
    const float omb  = 1.0f - beta;

#pragma unroll
    for (int t = 0; t < 4; t++) {                       // 4 tiles of 16 rows
        const int rb = t * 16;
        float acc0 = 0.f, acc1 = 0.f, acc2 = 0.f, acc3 = 0.f;
        const float4* s0 = (const float4*)rows[rb + r4 + 0];
        const float4* s1 = (const float4*)rows[rb + r4 + 4];
        const float4* s2 = (const float4*)rows[rb + r4 + 8];
        const float4* s3 = (const float4*)rows[rb + r4 + 12];
#pragma unroll
        for (int kk = 0; kk < DF / 4; kk++) {
            float4 a0 = s0[kk], a1 = s1[kk], a2 = s2[kk], a3 = s3[kk];
            float w0 = wcol[4 * kk], w1 = wcol[4 * kk + 1],
                  w2 = wcol[4 * kk + 2], w3 = wcol[4 * kk + 3];
            acc0 = fmaf(a0.x, w0, acc0); acc0 = fmaf(a0.y, w1, acc0);
            acc0 = fmaf(a0.z, w2, acc0); acc0 = fmaf(a0.w, w3, acc0);
            acc1 = fmaf(a1.x, w0, acc1); acc1 = fmaf(a1.y, w1, acc1);
            acc1 = fmaf(a1.z, w2, acc1); acc1 = fmaf(a1.w, w3, acc1);
            acc2 = fmaf(a2.x, w0, acc2); acc2 = fmaf(a2.y, w1, acc2);
            acc2 = fmaf(a2.z, w2, acc2); acc2 = fmaf(a2.w, w3, acc2);
            acc3 = fmaf(a3.x, w0, acc3); acc3 = fmaf(a3.y, w1, acc3);
            acc3 = fmaf(a3.z, w2, acc3); acc3 = fmaf(a3.w, w3, acc3);
        }
        const size_t gb = (size_t)blockIdx.x * 64 + rb;
        out[(gb + r4 +  0) * DF + j] = omb * rows[rb + r4 +  0][j] + beta * acc0;
        out[(gb + r4 +  4) * DF + j] = omb * rows[rb + r4 +  4][j] + beta * acc1;
        out[(gb + r4 +  8) * DF + j] = omb * rows[rb + r4 +  8][j] + beta * acc2;
        out[(gb + r4 + 12) * DF + j] = omb * rows[rb + r4 + 12][j] + beta * acc3;
    }
}

// ---------------------------------------------------------------------------
// Launch chain. Inputs: feature, x, adj_src, adj_dst, adj_val, weight,
// alpha, lamda, l. Output: float32 [N, D].
// ---------------------------------------------------------------------------
extern "C" void kernel_launch(void* const* d_in, const int* in_sizes, int n_in,
                              void* d_out, int out_size) {
    const float* feature = (const float*)d_in[0];
    const float* x       = (const float*)d_in[1];
    const int*   adj_src = (const int*)  d_in[2];
    const int*   adj_dst = (const int*)  d_in[3];
    const float* adj_val = (const float*)d_in[4];
    const float* weight  = (const float*)d_in[5];
    const float* alpha   = (const float*)d_in[6];
    const float* lamda   = (const float*)d_in[7];
    const int*   l_p     = (n_in >= 9) ? (const int*)d_in[8] : nullptr;
    float* out = (float*)d_out;
    (void)in_sizes; (void)out_size;

    k_zero <<<NNODES / 1024, 1024>>>();
    k_bin  <<<(NEDGES / 4) / 256, 256>>>(adj_src, adj_dst, adj_val, alpha);
    k_fused<<<NNODES / 64, 256>>>(feature, x, weight, alpha, lamda, l_p, out);
}

// round 7
// speedup vs baseline: 1.0526x; 1.0526x over previous
#include <cuda_runtime.h>
#include <math.h>

#define NNODES 65536
#define DF 64
#define NEDGES 1048576
#define CAP 64            // per-node bin capacity (Poisson(16); never overflowed)
#define CHUNK 16

// ---- static scratch (no device allocs allowed) ----
__device__ int   g_cnt[NNODES];            // per-node fill cursor / count
__device__ int2  g_ew[NNODES * CAP];       // bins: (.x = src, .y = bits of (1-alpha)*val)
__device__ float g_irc[NNODES * DF];       // aggregated + residual rows

// ---------------------------------------------------------------------------
// 1) zero cursors (globals dirty across graph replays). int4 stores.
// ---------------------------------------------------------------------------
__global__ void k_zero() {
    ((int4*)g_cnt)[blockIdx.x * blockDim.x + threadIdx.x] = make_int4(0, 0, 0, 0);
}

// ---------------------------------------------------------------------------
// 2) bin edges by destination; fold (1-alpha)*val into stored weight.
//    8 edges per thread -> 8 independent atomics in flight.
// ---------------------------------------------------------------------------
__global__ void k_bin(const int*   __restrict__ src,
                      const int*   __restrict__ dst,
                      const float* __restrict__ val,
                      const float* __restrict__ alpha_p) {
    const int t = blockIdx.x * blockDim.x + threadIdx.x;   // 0 .. NEDGES/8-1
    const float oma = 1.0f - __ldg(alpha_p);

    int4   sa = __ldg((const int4*)src + 2 * t);
    int4   sb = __ldg((const int4*)src + 2 * t + 1);
    int4   da = __ldg((const int4*)dst + 2 * t);
    int4   db = __ldg((const int4*)dst + 2 * t + 1);
    float4 va = __ldg((const float4*)val + 2 * t);
    float4 vb = __ldg((const float4*)val + 2 * t + 1);

    int s[8] = { sa.x, sa.y, sa.z, sa.w, sb.x, sb.y, sb.z, sb.w };
    int d[8] = { da.x, da.y, da.z, da.w, db.x, db.y, db.z, db.w };
    float v[8] = { va.x, va.y, va.z, va.w, vb.x, vb.y, vb.z, vb.w };

    int p[8];
#pragma unroll
    for (int i = 0; i < 8; i++) p[i] = atomicAdd(&g_cnt[d[i]], 1);
#pragma unroll
    for (int i = 0; i < 8; i++)
        if (p[i] < CAP)
            g_ew[(size_t)d[i] * CAP + p[i]] = make_int2(s[i], __float_as_int(oma * v[i]));
}

// ---------------------------------------------------------------------------
// 3) gather-aggregate: warp per node (8 nodes/warp serial), lane owns 2 cols.
//    Degrees prefetched for all 8 nodes; edge records staged in shared;
//    16 gathers in flight per chunk.
// ---------------------------------------------------------------------------
__global__ void __launch_bounds__(256) k_gather(const float* __restrict__ feature,
                                                const float* __restrict__ x,
                                                const float* __restrict__ alpha_p) {
    __shared__ int2 sew[8][CAP];           // 4 KB

    const int tid  = threadIdx.x;
    const int wid  = tid >> 5;
    const int lane = tid & 31;
    const int base = blockIdx.x * 64 + wid * 8;

    // prefetch all 8 node degrees (one coalesced load, then shfl)
    int mycnt = (lane < 8) ? g_cnt[base + lane] : 0;

    const float  alpha = __ldg(alpha_p);
    const float2* x2   = (const float2*)x;

    for (int t = 0; t < 8; t++) {
        const int node = base + t;
        int cnt = __shfl_sync(0xffffffffu, mycnt, t);
        if (cnt > CAP) cnt = CAP;
        const int padded = (cnt + CHUNK - 1) & ~(CHUNK - 1);

        const int2* row = g_ew + (size_t)node * CAP;
        __syncwarp();                                   // prior-iter readers done
        if (lane < cnt)      sew[wid][lane]      = __ldg(row + lane);
        if (lane + 32 < cnt) sew[wid][lane + 32] = __ldg(row + lane + 32);
        for (int i = cnt + lane; i < padded; i += 32)
            sew[wid][i] = make_int2(0, 0);              // src 0, weight 0 -> no-op
        __syncwarp();

        float2 f = __ldg((const float2*)feature + (size_t)node * 32 + lane);
        float2 acc = make_float2(alpha * f.x, alpha * f.y);

        for (int cb = 0; cb < padded; cb += CHUNK) {
            int2 e[CHUNK];
#pragma unroll
            for (int i = 0; i < CHUNK; i++) e[i] = sew[wid][cb + i];  // LDS broadcast
            float2 xv[CHUNK];
#pragma unroll
            for (int i = 0; i < CHUNK; i++)                           // 16 LDGs in flight
                xv[i] = __ldg(&x2[(size_t)e[i].x * 32 + lane]);
#pragma unroll
            for (int i = 0; i < CHUNK; i++) {
                float w = __int_as_float(e[i].y);
                acc.x = fmaf(w, xv[i].x, acc.x);
                acc.y = fmaf(w, xv[i].y, acc.y);
            }
        }

        ((float2*)g_irc)[(size_t)node * 32 + lane] = acc;
    }
}

// ---------------------------------------------------------------------------
// 4) out = (1-beta)*irc + beta*(irc @ W), split-k GEMM.
//    Block 256, 64 rows. Thread (h=tid&1, j=(tid>>1)&63, g=tid>>7):
//    holds 32 W regs (half a column: float4s kk*2+h of each row), computes
//    half-dots for rows of group g, combines halves via shfl_xor(1).
//    Interleaved f4 indexing keeps the h=0/h=1 LDS pair 16B apart (1 wavefront).
//    32 wcol regs (vs 64) -> 3 blocks/SM.
// ---------------------------------------------------------------------------
__global__ void __launch_bounds__(256, 3)
k_gemm(const float* __restrict__ weight,
       const float* __restrict__ lamda_p,
       const int*   __restrict__ l_p,
       float*       __restrict__ out) {
    __shared__ __align__(16) float rows[64 * DF];       // 16 KB

    const int tid = threadIdx.x;

    // stage 64 irc rows (coalesced float4)
    const float4* irc4 = (const float4*)g_irc;
    const size_t b4 = (size_t)blockIdx.x * 1024;        // 64 rows * 16 f4
    float4* r4s = (float4*)rows;
#pragma unroll
    for (int i = 0; i < 4; i++)
        r4s[tid + 256 * i] = __ldg(irc4 + b4 + tid + 256 * i);

    const int h = tid & 1;
    const int j = (tid >> 1) & 63;
    const int g = tid >> 7;

    // half-column of W: covers k = (kk*2+h)*4 + c, kk=0..7, c=0..3
    float wcol[32];
#pragma unroll
    for (int kk = 0; kk < 8; kk++)
#pragma unroll
        for (int c = 0; c < 4; c++)
            wcol[kk * 4 + c] = __ldg(weight + ((kk * 2 + h) * 4 + c) * DF + j);

    const float lam  = __ldg(lamda_p);
    const int   l    = (l_p != nullptr) ? __ldg(l_p) : 1;
    const float beta = logf(lam / (float)l + 1.0f);
    const float omb  = 1.0f - beta;

    __syncthreads();

    const size_t gbase = (size_t)blockIdx.x * 64;
#pragma unroll 2
    for (int rr = 0; rr < 16; rr++) {
        const int r0 = g * 32 + rr * 2;
        const float4* ra = (const float4*)rows + r0 * 16 + h;
        const float4* rb = ra + 16;
        float acc0 = 0.f, acc1 = 0.f;
#pragma unroll
        for (int kk = 0; kk < 8; kk++) {
            float4 a = ra[kk * 2];
            float4 b = rb[kk * 2];
            acc0 = fmaf(a.x, wcol[kk * 4 + 0], acc0);
            acc0 = fmaf(a.y, wcol[kk * 4 + 1], acc0);
            acc0 = fmaf(a.z, wcol[kk * 4 + 2], acc0);
            acc0 = fmaf(a.w, wcol[kk * 4 + 3], acc0);
            acc1 = fmaf(b.x, wcol[kk * 4 + 0], acc1);
            acc1 = fmaf(b.y, wcol[kk * 4 + 1], acc1);
            acc1 = fmaf(b.z, wcol[kk * 4 + 2], acc1);
            acc1 = fmaf(b.w, wcol[kk * 4 + 3], acc1);
        }
        acc0 += __shfl_xor_sync(0xffffffffu, acc0, 1);   // combine k-halves
        acc1 += __shfl_xor_sync(0xffffffffu, acc1, 1);
        if (h == 0) {
            out[(gbase + r0)     * DF + j] = omb * rows[r0 * DF + j]       + beta * acc0;
            out[(gbase + r0 + 1) * DF + j] = omb * rows[(r0 + 1) * DF + j] + beta * acc1;
        }
    }
}

// ---------------------------------------------------------------------------
// Launch chain. Inputs: feature, x, adj_src, adj_dst, adj_val, weight,
// alpha, lamda, l. Output: float32 [N, D].
// ---------------------------------------------------------------------------
extern "C" void kernel_launch(void* const* d_in, const int* in_sizes, int n_in,
                              void* d_out, int out_size) {
    const float* feature = (const float*)d_in[0];
    const float* x       = (const float*)d_in[1];
    const int*   adj_src = (const int*)  d_in[2];
    const int*   adj_dst = (const int*)  d_in[3];
    const float* adj_val = (const float*)d_in[4];
    const float* weight  = (const float*)d_in[5];
    const float* alpha   = (const float*)d_in[6];
    const float* lamda   = (const float*)d_in[7];
    const int*   l_p     = (n_in >= 9) ? (const int*)d_in[8] : nullptr;
    float* out = (float*)d_out;
    (void)in_sizes; (void)out_size;

    k_zero  <<<NNODES / 4 / 128, 128>>>();
    k_bin   <<<(NEDGES / 8) / 256, 256>>>(adj_src, adj_dst, adj_val, alpha);
    k_gather<<<NNODES / 64, 256>>>(feature, x, alpha);
    k_gemm  <<<NNODES / 64, 256>>>(weight, lamda, l_p, out);
}